// round 8
// baseline (speedup 1.0000x reference)
#include <cuda_runtime.h>

// SSIM map: 3x3 mean filter (reflect pad 1) fused, fp32 in/out.
// All-scalar math (R0 structure) + software-pipelined row prefetch,
// STRIP=16, shared-subsum horizontal, x81^2-rescaled SSIM epilogue.
// Shapes fixed: planes = N*C = 96, H=384, W=640.

#define HH 384
#define WW 640
#define STRIP 16         // output rows per thread
#define TPB 160          // 160 threads * 4 cols = 640 = full width

__device__ __forceinline__ int rrow(int r) {
    // reflect index for pad=1: -1 -> 1, H+k -> H-2-k
    return r < 0 ? -r : (r >= HH ? 2 * HH - 2 - r : r);
}

__device__ __forceinline__ void load_row6(const float* __restrict__ base,
                                          int c0, int cm1, int cp4,
                                          float dst[6]) {
    float4 v = *(const float4*)(base + c0);
    float a = __ldg(base + cm1);
    float b = __ldg(base + cp4);
    dst[0] = a;
    dst[1] = v.x; dst[2] = v.y; dst[3] = v.z; dst[4] = v.w;
    dst[5] = b;
}

__global__ __launch_bounds__(TPB)
void ssim_kernel(const float* __restrict__ x,
                 const float* __restrict__ y,
                 float* __restrict__ out)
{
    const int tx    = threadIdx.x;
    const int c0    = tx * 4;
    const int plane = blockIdx.y;
    const int r0    = blockIdx.x * STRIP;

    const size_t pbase = (size_t)plane * HH * WW;
    const float* xp = x + pbase;
    const float* yp = y + pbase;
    float* op       = out + pbase;

    const int cm1 = (c0 == 0) ? 1 : c0 - 1;
    const int cp4 = (c0 + 4 >= WW) ? (WW - 2) : (c0 + 4);

    // Rescaled constants: num and den both carry x81^2, which cancels.
    const float C1S = 81.0f * 1.0e-4f;   // 81*C1
    const float C2S = 81.0f * 9.0e-4f;   // 81*C2

    // 3-row rotating register buffers: 6 columns (c0-1 .. c0+4), x and y.
    float xr[3][6], yr[3][6];

    // Preload rows r0-1, r0, r0+1 into slots 0,1,2.
    #pragma unroll
    for (int k = 0; k < 3; k++) {
        const int r = rrow(r0 - 1 + k);
        load_row6(xp + (size_t)r * WW, c0, cm1, cp4, xr[k]);
        load_row6(yp + (size_t)r * WW, c0, cm1, cp4, yr[k]);
    }

    #pragma unroll
    for (int i = 0; i < STRIP; i++) {
        // ---- Prefetch row r0+i+2 (consumed NEXT iteration) ----
        float px[6], py[6];
        {
            const int r = rrow(r0 + i + 2);   // reflect keeps it in range
            load_row6(xp + (size_t)r * WW, c0, cm1, cp4, px);
            load_row6(yp + (size_t)r * WW, c0, cm1, cp4, py);
        }

        const int s0 = i % 3, s1 = (i + 1) % 3, s2 = (i + 2) % 3;

        // ---- Vertical (column) sums over 3 rows for all 6 columns ----
        float sx[6], sy[6], sxx[6], syy[6], sxy[6];
        #pragma unroll
        for (int j = 0; j < 6; j++) {
            const float a0 = xr[s0][j], a1 = xr[s1][j], a2 = xr[s2][j];
            const float b0 = yr[s0][j], b1 = yr[s1][j], b2 = yr[s2][j];
            sx[j]  = a0 + a1 + a2;
            sy[j]  = b0 + b1 + b2;
            sxx[j] = fmaf(a0, a0, fmaf(a1, a1, a2 * a2));
            syy[j] = fmaf(b0, b0, fmaf(b1, b1, b2 * b2));
            sxy[j] = fmaf(a0, b0, fmaf(a1, b1, a2 * b2));
        }

        // ---- Horizontal 3-sums via shared sub-sums (6 adds per stat) ----
        // outputs o=0..3 need cols j=o..o+2; u=j1+j2, v=j3+j4:
        // S0=j0+u, S1=u+j3, S2=j2+v, S3=v+j5
        float Sx[4], Sy[4], Sxx[4], Syy[4], Sxy[4];
        {
            float u, v;
            u = sx[1] + sx[2];   v = sx[3] + sx[4];
            Sx[0] = sx[0] + u;  Sx[1] = u + sx[3];  Sx[2] = sx[2] + v;  Sx[3] = v + sx[5];
            u = sy[1] + sy[2];   v = sy[3] + sy[4];
            Sy[0] = sy[0] + u;  Sy[1] = u + sy[3];  Sy[2] = sy[2] + v;  Sy[3] = v + sy[5];
            u = sxx[1] + sxx[2]; v = sxx[3] + sxx[4];
            Sxx[0] = sxx[0] + u; Sxx[1] = u + sxx[3]; Sxx[2] = sxx[2] + v; Sxx[3] = v + sxx[5];
            u = syy[1] + syy[2]; v = syy[3] + syy[4];
            Syy[0] = syy[0] + u; Syy[1] = u + syy[3]; Syy[2] = syy[2] + v; Syy[3] = v + syy[5];
            u = sxy[1] + sxy[2]; v = sxy[3] + sxy[4];
            Sxy[0] = sxy[0] + u; Sxy[1] = u + sxy[3]; Sxy[2] = sxy[2] + v; Sxy[3] = v + sxy[5];
        }

        // ---- SSIM, rescaled by 81^2 (cancels in the ratio) ----
        float resv[4];
        #pragma unroll
        for (int o = 0; o < 4; o++) {
            const float P  = Sx[o] * Sy[o];
            const float Qx = Sx[o] * Sx[o];
            const float Qy = Sy[o] * Sy[o];
            const float A  = fmaf(Sxx[o], 9.0f, -Qx);   // 9*Sxx - Sx^2  (FFMA-imm)
            const float B  = fmaf(Syy[o], 9.0f, -Qy);
            const float Cc = fmaf(Sxy[o], 9.0f, -P);
            const float num = fmaf(P, 2.0f, C1S) * fmaf(Cc, 2.0f, C2S);
            const float den = (Qx + Qy + C1S) * (A + B + C2S);
            float s = __fdividef(num, den);
            resv[o] = fminf(fmaxf(s, 0.0f), 1.0f);
        }

        float4 res = make_float4(resv[0], resv[1], resv[2], resv[3]);
        *(float4*)(op + (size_t)(r0 + i) * WW + c0) = res;

        // ---- Commit prefetched row into the retiring slot (renamed away
        //      by ptxas thanks to full unroll) ----
        #pragma unroll
        for (int j = 0; j < 6; j++) { xr[s0][j] = px[j]; yr[s0][j] = py[j]; }
    }
}

extern "C" void kernel_launch(void* const* d_in, const int* in_sizes, int n_in,
                              void* d_out, int out_size) {
    const float* x = (const float*)d_in[0];
    const float* y = (const float*)d_in[1];
    float* out = (float*)d_out;

    const int planes = in_sizes[0] / (HH * WW);   // 96
    dim3 grid(HH / STRIP, planes);                // (24, 96)
    ssim_kernel<<<grid, TPB>>>(x, y, out);
}

// round 9
// speedup vs baseline: 1.0609x; 1.0609x over previous
#include <cuda_runtime.h>

// SSIM map: 3x3 mean filter (reflect pad 1) fused, fp32 in/out.
// Proven R0 structure (STRIP=8, all-scalar, rotating 3-row register buffer)
// + shared-subsum horizontal sums + x81^2-rescaled SSIM epilogue.
// Shapes fixed: planes = N*C = 96, H=384, W=640.

#define HH 384
#define WW 640
#define STRIP 8          // output rows per thread
#define TPB 160          // 160 threads * 4 cols = 640 = full width

__device__ __forceinline__ int rrow(int r) {
    // reflect index for pad=1: -1 -> 1, H -> H-2
    return r < 0 ? -r : (r >= HH ? 2 * HH - 2 - r : r);
}

__device__ __forceinline__ void load_row6(const float* __restrict__ base,
                                          int c0, int cm1, int cp4,
                                          float dst[6]) {
    float4 v = *(const float4*)(base + c0);
    dst[0] = __ldg(base + cm1);
    dst[1] = v.x; dst[2] = v.y; dst[3] = v.z; dst[4] = v.w;
    dst[5] = __ldg(base + cp4);
}

__global__ __launch_bounds__(TPB)
void ssim_kernel(const float* __restrict__ x,
                 const float* __restrict__ y,
                 float* __restrict__ out)
{
    const int tx    = threadIdx.x;
    const int c0    = tx * 4;
    const int plane = blockIdx.y;
    const int r0    = blockIdx.x * STRIP;

    const size_t pbase = (size_t)plane * HH * WW;
    const float* xp = x + pbase;
    const float* yp = y + pbase;
    float* op       = out + pbase;

    const int cm1 = (c0 == 0) ? 1 : c0 - 1;
    const int cp4 = (c0 + 4 >= WW) ? (WW - 2) : (c0 + 4);

    // Rescaled constants: num and den both carry x81^2, which cancels.
    const float C1S = 81.0f * 1.0e-4f;   // 81*C1
    const float C2S = 81.0f * 9.0e-4f;   // 81*C2

    // 3-row rotating register buffers: 6 columns (c0-1 .. c0+4), x and y.
    float xr[3][6], yr[3][6];

    // Preload rows r0-1 and r0 into slots 0 and 1.
    #pragma unroll
    for (int k = 0; k < 2; k++) {
        const int r = rrow(r0 - 1 + k);
        load_row6(xp + (size_t)r * WW, c0, cm1, cp4, xr[k]);
        load_row6(yp + (size_t)r * WW, c0, cm1, cp4, yr[k]);
    }

    #pragma unroll
    for (int i = 0; i < STRIP; i++) {
        // Load input row (r0 + i + 1) into the rotating slot.
        {
            const int slot = (i + 2) % 3;
            const int r = rrow(r0 + i + 1);
            load_row6(xp + (size_t)r * WW, c0, cm1, cp4, xr[slot]);
            load_row6(yp + (size_t)r * WW, c0, cm1, cp4, yr[slot]);
        }

        const int s0 = i % 3, s1 = (i + 1) % 3, s2 = (i + 2) % 3;

        // ---- Vertical (column) sums over 3 rows for all 6 columns ----
        float sx[6], sy[6], sxx[6], syy[6], sxy[6];
        #pragma unroll
        for (int j = 0; j < 6; j++) {
            const float a0 = xr[s0][j], a1 = xr[s1][j], a2 = xr[s2][j];
            const float b0 = yr[s0][j], b1 = yr[s1][j], b2 = yr[s2][j];
            sx[j]  = a0 + a1 + a2;
            sy[j]  = b0 + b1 + b2;
            sxx[j] = fmaf(a0, a0, fmaf(a1, a1, a2 * a2));
            syy[j] = fmaf(b0, b0, fmaf(b1, b1, b2 * b2));
            sxy[j] = fmaf(a0, b0, fmaf(a1, b1, a2 * b2));
        }

        // ---- Horizontal 3-sums via shared sub-sums (6 adds per stat) ----
        // u=j1+j2, v=j3+j4: S0=j0+u, S1=u+j3, S2=j2+v, S3=v+j5
        float Sx[4], Sy[4], Sxx[4], Syy[4], Sxy[4];
        {
            float u, v;
            u = sx[1] + sx[2];   v = sx[3] + sx[4];
            Sx[0] = sx[0] + u;  Sx[1] = u + sx[3];  Sx[2] = sx[2] + v;  Sx[3] = v + sx[5];
            u = sy[1] + sy[2];   v = sy[3] + sy[4];
            Sy[0] = sy[0] + u;  Sy[1] = u + sy[3];  Sy[2] = sy[2] + v;  Sy[3] = v + sy[5];
            u = sxx[1] + sxx[2]; v = sxx[3] + sxx[4];
            Sxx[0] = sxx[0] + u; Sxx[1] = u + sxx[3]; Sxx[2] = sxx[2] + v; Sxx[3] = v + sxx[5];
            u = syy[1] + syy[2]; v = syy[3] + syy[4];
            Syy[0] = syy[0] + u; Syy[1] = u + syy[3]; Syy[2] = syy[2] + v; Syy[3] = v + syy[5];
            u = sxy[1] + sxy[2]; v = sxy[3] + sxy[4];
            Sxy[0] = sxy[0] + u; Sxy[1] = u + sxy[3]; Sxy[2] = sxy[2] + v; Sxy[3] = v + sxy[5];
        }

        // ---- SSIM, rescaled by 81^2 (cancels in the ratio) ----
        float resv[4];
        #pragma unroll
        for (int o = 0; o < 4; o++) {
            const float P  = Sx[o] * Sy[o];
            const float Qx = Sx[o] * Sx[o];
            const float Qy = Sy[o] * Sy[o];
            const float A  = fmaf(Sxx[o], 9.0f, -Qx);   // 9*Sxx - Sx^2  (FFMA-imm)
            const float B  = fmaf(Syy[o], 9.0f, -Qy);
            const float Cc = fmaf(Sxy[o], 9.0f, -P);
            const float num = fmaf(P, 2.0f, C1S) * fmaf(Cc, 2.0f, C2S);
            const float den = (Qx + Qy + C1S) * (A + B + C2S);
            float s = __fdividef(num, den);
            resv[o] = fminf(fmaxf(s, 0.0f), 1.0f);
        }

        float4 res = make_float4(resv[0], resv[1], resv[2], resv[3]);
        *(float4*)(op + (size_t)(r0 + i) * WW + c0) = res;
    }
}

extern "C" void kernel_launch(void* const* d_in, const int* in_sizes, int n_in,
                              void* d_out, int out_size) {
    const float* x = (const float*)d_in[0];
    const float* y = (const float*)d_in[1];
    float* out = (float*)d_out;

    const int planes = in_sizes[0] / (HH * WW);   // 96
    dim3 grid(HH / STRIP, planes);                // (48, 96)
    ssim_kernel<<<grid, TPB>>>(x, y, out);
}

// round 10
// speedup vs baseline: 1.0974x; 1.0344x over previous
#include <cuda_runtime.h>

// SSIM map: 3x3 mean filter (reflect pad 1) fused, fp32 in/out.
// R8 body (STRIP=8, all-scalar, shared-subsum horizontal, x81^2 epilogue)
// + __launch_bounds__(160, 6) to force 6 CTAs/SM (occ 35% -> 47%):
// the kernel is latency-bound, not pipe-bound; warp supply is the lever.
// Shapes fixed: planes = N*C = 96, H=384, W=640.

#define HH 384
#define WW 640
#define STRIP 8          // output rows per thread
#define TPB 160          // 160 threads * 4 cols = 640 = full width

__device__ __forceinline__ int rrow(int r) {
    // reflect index for pad=1: -1 -> 1, H -> H-2
    return r < 0 ? -r : (r >= HH ? 2 * HH - 2 - r : r);
}

__device__ __forceinline__ void load_row6(const float* __restrict__ base,
                                          int c0, int cm1, int cp4,
                                          float dst[6]) {
    float4 v = *(const float4*)(base + c0);
    dst[0] = __ldg(base + cm1);
    dst[1] = v.x; dst[2] = v.y; dst[3] = v.z; dst[4] = v.w;
    dst[5] = __ldg(base + cp4);
}

__global__ __launch_bounds__(TPB, 6)
void ssim_kernel(const float* __restrict__ x,
                 const float* __restrict__ y,
                 float* __restrict__ out)
{
    const int tx    = threadIdx.x;
    const int c0    = tx * 4;
    const int plane = blockIdx.y;
    const int r0    = blockIdx.x * STRIP;

    const size_t pbase = (size_t)plane * HH * WW;
    const float* xp = x + pbase;
    const float* yp = y + pbase;
    float* op       = out + pbase;

    const int cm1 = (c0 == 0) ? 1 : c0 - 1;
    const int cp4 = (c0 + 4 >= WW) ? (WW - 2) : (c0 + 4);

    // Rescaled constants: num and den both carry x81^2, which cancels.
    const float C1S = 81.0f * 1.0e-4f;   // 81*C1
    const float C2S = 81.0f * 9.0e-4f;   // 81*C2

    // 3-row rotating register buffers: 6 columns (c0-1 .. c0+4), x and y.
    float xr[3][6], yr[3][6];

    // Preload rows r0-1 and r0 into slots 0 and 1.
    #pragma unroll
    for (int k = 0; k < 2; k++) {
        const int r = rrow(r0 - 1 + k);
        load_row6(xp + (size_t)r * WW, c0, cm1, cp4, xr[k]);
        load_row6(yp + (size_t)r * WW, c0, cm1, cp4, yr[k]);
    }

    #pragma unroll
    for (int i = 0; i < STRIP; i++) {
        // Load input row (r0 + i + 1) into the rotating slot.
        {
            const int slot = (i + 2) % 3;
            const int r = rrow(r0 + i + 1);
            load_row6(xp + (size_t)r * WW, c0, cm1, cp4, xr[slot]);
            load_row6(yp + (size_t)r * WW, c0, cm1, cp4, yr[slot]);
        }

        const int s0 = i % 3, s1 = (i + 1) % 3, s2 = (i + 2) % 3;

        // ---- Vertical (column) sums over 3 rows for all 6 columns ----
        float sx[6], sy[6], sxx[6], syy[6], sxy[6];
        #pragma unroll
        for (int j = 0; j < 6; j++) {
            const float a0 = xr[s0][j], a1 = xr[s1][j], a2 = xr[s2][j];
            const float b0 = yr[s0][j], b1 = yr[s1][j], b2 = yr[s2][j];
            sx[j]  = a0 + a1 + a2;
            sy[j]  = b0 + b1 + b2;
            sxx[j] = fmaf(a0, a0, fmaf(a1, a1, a2 * a2));
            syy[j] = fmaf(b0, b0, fmaf(b1, b1, b2 * b2));
            sxy[j] = fmaf(a0, b0, fmaf(a1, b1, a2 * b2));
        }

        // ---- Horizontal 3-sums via shared sub-sums (6 adds per stat) ----
        // u=j1+j2, v=j3+j4: S0=j0+u, S1=u+j3, S2=j2+v, S3=v+j5
        float Sx[4], Sy[4], Sxx[4], Syy[4], Sxy[4];
        {
            float u, v;
            u = sx[1] + sx[2];   v = sx[3] + sx[4];
            Sx[0] = sx[0] + u;  Sx[1] = u + sx[3];  Sx[2] = sx[2] + v;  Sx[3] = v + sx[5];
            u = sy[1] + sy[2];   v = sy[3] + sy[4];
            Sy[0] = sy[0] + u;  Sy[1] = u + sy[3];  Sy[2] = sy[2] + v;  Sy[3] = v + sy[5];
            u = sxx[1] + sxx[2]; v = sxx[3] + sxx[4];
            Sxx[0] = sxx[0] + u; Sxx[1] = u + sxx[3]; Sxx[2] = sxx[2] + v; Sxx[3] = v + sxx[5];
            u = syy[1] + syy[2]; v = syy[3] + syy[4];
            Syy[0] = syy[0] + u; Syy[1] = u + syy[3]; Syy[2] = syy[2] + v; Syy[3] = v + syy[5];
            u = sxy[1] + sxy[2]; v = sxy[3] + sxy[4];
            Sxy[0] = sxy[0] + u; Sxy[1] = u + sxy[3]; Sxy[2] = sxy[2] + v; Sxy[3] = v + sxy[5];
        }

        // ---- SSIM, rescaled by 81^2 (cancels in the ratio) ----
        float resv[4];
        #pragma unroll
        for (int o = 0; o < 4; o++) {
            const float P  = Sx[o] * Sy[o];
            const float Qx = Sx[o] * Sx[o];
            const float Qy = Sy[o] * Sy[o];
            const float A  = fmaf(Sxx[o], 9.0f, -Qx);   // 9*Sxx - Sx^2  (FFMA-imm)
            const float B  = fmaf(Syy[o], 9.0f, -Qy);
            const float Cc = fmaf(Sxy[o], 9.0f, -P);
            const float num = fmaf(P, 2.0f, C1S) * fmaf(Cc, 2.0f, C2S);
            const float den = (Qx + Qy + C1S) * (A + B + C2S);
            float s = __fdividef(num, den);
            resv[o] = fminf(fmaxf(s, 0.0f), 1.0f);
        }

        float4 res = make_float4(resv[0], resv[1], resv[2], resv[3]);
        *(float4*)(op + (size_t)(r0 + i) * WW + c0) = res;
    }
}

extern "C" void kernel_launch(void* const* d_in, const int* in_sizes, int n_in,
                              void* d_out, int out_size) {
    const float* x = (const float*)d_in[0];
    const float* y = (const float*)d_in[1];
    float* out = (float*)d_out;

    const int planes = in_sizes[0] / (HH * WW);   // 96
    dim3 grid(HH / STRIP, planes);                // (48, 96)
    ssim_kernel<<<grid, TPB>>>(x, y, out);
}

// round 11
// speedup vs baseline: 1.1234x; 1.0237x over previous
#include <cuda_runtime.h>

// SSIM map: 3x3 mean filter (reflect pad 1) fused, fp32 in/out.
// 8-wide per-thread tiles (2x float4 loads): doubled ILP/MLP per warp,
// edge-halo cost amortized over 8 outputs. Shared-subsum horizontal,
// x81^2-rescaled epilogue. Shapes fixed: planes=96, H=384, W=640.

#define HH 384
#define WW 640
#define STRIP 8            // output rows per thread
#define TPW 80             // threads per row-strip: 80 * 8 cols = 640
#define ROWS_PER_BLK 2     // row-strips per block
#define TPB (TPW * ROWS_PER_BLK)   // 160 threads

__device__ __forceinline__ int rrow(int r) {
    // reflect index for pad=1: -1 -> 1, H -> H-2
    return r < 0 ? -r : (r >= HH ? 2 * HH - 2 - r : r);
}

// Load 10 columns (c0-1 .. c0+8) of one row.
__device__ __forceinline__ void load_row10(const float* __restrict__ base,
                                           int c0, int cm1, int cp8,
                                           float d[10]) {
    float4 v = *(const float4*)(base + c0);
    float4 w = *(const float4*)(base + c0 + 4);
    d[0] = __ldg(base + cm1);
    d[1] = v.x; d[2] = v.y; d[3] = v.z; d[4] = v.w;
    d[5] = w.x; d[6] = w.y; d[7] = w.z; d[8] = w.w;
    d[9] = __ldg(base + cp8);
}

__global__ __launch_bounds__(TPB)
void ssim_kernel(const float* __restrict__ x,
                 const float* __restrict__ y,
                 float* __restrict__ out)
{
    const int tid   = threadIdx.x;
    const int tx    = tid % TPW;
    const int ty    = tid / TPW;
    const int c0    = tx * 8;
    const int plane = blockIdx.y;
    const int r0    = (blockIdx.x * ROWS_PER_BLK + ty) * STRIP;

    const size_t pbase = (size_t)plane * HH * WW;
    const float* xp = x + pbase;
    const float* yp = y + pbase;
    float* op       = out + pbase;

    const int cm1 = (c0 == 0) ? 1 : c0 - 1;
    const int cp8 = (c0 + 8 >= WW) ? (WW - 2) : (c0 + 8);

    // Rescaled constants: num and den both carry x81^2, which cancels.
    const float C1S = 81.0f * 1.0e-4f;   // 81*C1
    const float C2S = 81.0f * 9.0e-4f;   // 81*C2

    // 3-row rotating register buffers: 10 columns (c0-1 .. c0+8), x and y.
    float xr[3][10], yr[3][10];

    // Preload rows r0-1 and r0 into slots 0 and 1.
    #pragma unroll
    for (int k = 0; k < 2; k++) {
        const int r = rrow(r0 - 1 + k);
        load_row10(xp + (size_t)r * WW, c0, cm1, cp8, xr[k]);
        load_row10(yp + (size_t)r * WW, c0, cm1, cp8, yr[k]);
    }

    #pragma unroll
    for (int i = 0; i < STRIP; i++) {
        // Load input row (r0 + i + 1) into the rotating slot.
        {
            const int slot = (i + 2) % 3;
            const int r = rrow(r0 + i + 1);
            load_row10(xp + (size_t)r * WW, c0, cm1, cp8, xr[slot]);
            load_row10(yp + (size_t)r * WW, c0, cm1, cp8, yr[slot]);
        }

        const int s0 = i % 3, s1 = (i + 1) % 3, s2 = (i + 2) % 3;

        // ---- Vertical (column) sums over 3 rows for all 10 columns ----
        float sx[10], sy[10], sxx[10], syy[10], sxy[10];
        #pragma unroll
        for (int j = 0; j < 10; j++) {
            const float a0 = xr[s0][j], a1 = xr[s1][j], a2 = xr[s2][j];
            const float b0 = yr[s0][j], b1 = yr[s1][j], b2 = yr[s2][j];
            sx[j]  = a0 + a1 + a2;
            sy[j]  = b0 + b1 + b2;
            sxx[j] = fmaf(a0, a0, fmaf(a1, a1, a2 * a2));
            syy[j] = fmaf(b0, b0, fmaf(b1, b1, b2 * b2));
            sxy[j] = fmaf(a0, b0, fmaf(a1, b1, a2 * b2));
        }

        // ---- Horizontal 3-sums via shared pair-sums (12 adds per stat) ----
        // u1=s1+s2, u3=s3+s4, u5=s5+s6, u7=s7+s8:
        // S0=s0+u1, S1=u1+s3, S2=s2+u3, S3=u3+s5,
        // S4=s4+u5, S5=u5+s7, S6=s6+u7, S7=u7+s9
        float Sx[8], Sy[8], Sxx[8], Syy[8], Sxy[8];
        #define H8(S, s) { \
            const float u1 = s[1]+s[2], u3 = s[3]+s[4], u5 = s[5]+s[6], u7 = s[7]+s[8]; \
            S[0] = s[0]+u1; S[1] = u1+s[3]; S[2] = s[2]+u3; S[3] = u3+s[5]; \
            S[4] = s[4]+u5; S[5] = u5+s[7]; S[6] = s[6]+u7; S[7] = u7+s[9]; }
        H8(Sx,  sx);  H8(Sy,  sy);
        H8(Sxx, sxx); H8(Syy, syy); H8(Sxy, sxy);
        #undef H8

        // ---- SSIM, rescaled by 81^2 (cancels in the ratio) ----
        float resv[8];
        #pragma unroll
        for (int o = 0; o < 8; o++) {
            const float P  = Sx[o] * Sy[o];
            const float Qx = Sx[o] * Sx[o];
            const float Qy = Sy[o] * Sy[o];
            const float A  = fmaf(Sxx[o], 9.0f, -Qx);   // 9*Sxx - Sx^2 (FFMA-imm)
            const float B  = fmaf(Syy[o], 9.0f, -Qy);
            const float Cc = fmaf(Sxy[o], 9.0f, -P);
            const float num = fmaf(P, 2.0f, C1S) * fmaf(Cc, 2.0f, C2S);
            const float den = (Qx + Qy + C1S) * (A + B + C2S);
            float s = __fdividef(num, den);
            resv[o] = fminf(fmaxf(s, 0.0f), 1.0f);
        }

        float* orow = op + (size_t)(r0 + i) * WW + c0;
        *(float4*)(orow)     = make_float4(resv[0], resv[1], resv[2], resv[3]);
        *(float4*)(orow + 4) = make_float4(resv[4], resv[5], resv[6], resv[7]);
    }
}

extern "C" void kernel_launch(void* const* d_in, const int* in_sizes, int n_in,
                              void* d_out, int out_size) {
    const float* x = (const float*)d_in[0];
    const float* y = (const float*)d_in[1];
    float* out = (float*)d_out;

    const int planes = in_sizes[0] / (HH * WW);          // 96
    dim3 grid(HH / (STRIP * ROWS_PER_BLK), planes);      // (24, 96)
    ssim_kernel<<<grid, TPB>>>(x, y, out);
}